// round 10
// baseline (speedup 1.0000x reference)
#include <cuda_runtime.h>
#include <cuda_bf16.h>
#include <cstdint>

#define MAX_N 50000
#define MAX_E 800000
#define D 128

// Scratch in device globals.
__device__ int   g_is64;
__device__ int   g_deg[MAX_N];
__device__ int   g_off[MAX_N + 1];
__device__ int   g_cursor[MAX_N];
__device__ int   g_esrc[MAX_E];
__device__ int   g_bsum[64];
__device__ int   g_bpre[64];
__device__ __align__(16) float g_h[(size_t)MAX_N * D];

// ---------------------------------------------------------------------------
// Base-ISA tensor primitives (harness PTX target is sm_103 WITHOUT 'a':
// tcgen05 unavailable; mma.sync/ldmatrix are the tensor path).
// ---------------------------------------------------------------------------
__device__ __forceinline__ uint32_t smem_u32(const void* p) {
    uint32_t a;
    asm("{ .reg .u64 t; cvta.to.shared.u64 t, %1; cvt.u32.u64 %0, t; }" : "=r"(a) : "l"(p));
    return a;
}

#define LDSM_X4(r0, r1, r2, r3, addr) \
    asm volatile("ldmatrix.sync.aligned.m8n8.x4.shared.b16 {%0,%1,%2,%3}, [%4];" \
                 : "=r"(r0), "=r"(r1), "=r"(r2), "=r"(r3) : "r"(addr))

#define MMA16816(c, a, b0, b1) \
    asm volatile("mma.sync.aligned.m16n8k16.row.col.f32.bf16.bf16.f32 " \
                 "{%0,%1,%2,%3}, {%4,%5,%6,%7}, {%8,%9}, {%0,%1,%2,%3};" \
                 : "+f"((c)[0]), "+f"((c)[1]), "+f"((c)[2]), "+f"((c)[3]) \
                 : "r"((a)[0]), "r"((a)[1]), "r"((a)[2]), "r"((a)[3]), \
                   "r"(b0), "r"(b1))

// ---------------------------------------------------------------------------
// CSR build.  k_init: zero degrees + edge-dtype detect (dataset says int64,
// JAX default config emits int32 -> odd words all zero when truly int64).
// ---------------------------------------------------------------------------
__global__ void k_init(const int* __restrict__ ei32, int n) {
    int i = blockIdx.x * blockDim.x + threadIdx.x;
    if (i < n) g_deg[i] = 0;
    if (i == 0) {
        int allzero = 1;
        #pragma unroll
        for (int k = 1; k < 64; k += 2)
            if (ei32[k] != 0) allzero = 0;
        g_is64 = allzero;
    }
}

__device__ __forceinline__ int edge_at(const void* ei, int idx, int is64) {
    return is64 ? (int)((const long long*)ei)[idx] : ((const int*)ei)[idx];
}

__global__ void k_hist(const void* __restrict__ ei, int E) {
    int e = blockIdx.x * blockDim.x + threadIdx.x;
    int is64 = g_is64;
    if (e < E) atomicAdd(&g_deg[edge_at(ei, E + e, is64)], 1);
}

__global__ void k_scan_local(int n) {
    __shared__ int warp_sums[32];
    int lane = threadIdx.x & 31, wid = threadIdx.x >> 5;
    int i = blockIdx.x * 1024 + threadIdx.x;
    int v = (i < n) ? g_deg[i] : 0;
    int s = v;
    #pragma unroll
    for (int o = 1; o < 32; o <<= 1) {
        int t = __shfl_up_sync(0xFFFFFFFFu, s, o);
        if (lane >= o) s += t;
    }
    if (lane == 31) warp_sums[wid] = s;
    __syncthreads();
    if (wid == 0) {
        int ws = warp_sums[lane];
        #pragma unroll
        for (int o = 1; o < 32; o <<= 1) {
            int t = __shfl_up_sync(0xFFFFFFFFu, ws, o);
            if (lane >= o) ws += t;
        }
        warp_sums[lane] = ws;
    }
    __syncthreads();
    int incl = s + (wid > 0 ? warp_sums[wid - 1] : 0);
    if (i < n) g_off[i] = incl - v;
    if (threadIdx.x == 1023) g_bsum[blockIdx.x] = incl;
}

__global__ void k_scan_mid(int nb, int n) {
    int lane = threadIdx.x;
    int v0 = (lane < nb) ? g_bsum[lane] : 0;
    int v1 = (lane + 32 < nb) ? g_bsum[lane + 32] : 0;
    int s0 = v0;
    #pragma unroll
    for (int o = 1; o < 32; o <<= 1) {
        int t = __shfl_up_sync(0xFFFFFFFFu, s0, o);
        if (lane >= o) s0 += t;
    }
    int tot0 = __shfl_sync(0xFFFFFFFFu, s0, 31);
    int s1 = v1;
    #pragma unroll
    for (int o = 1; o < 32; o <<= 1) {
        int t = __shfl_up_sync(0xFFFFFFFFu, s1, o);
        if (lane >= o) s1 += t;
    }
    s1 += tot0;
    if (lane < nb) g_bpre[lane] = s0 - v0;
    if (lane + 32 < nb) g_bpre[lane + 32] = s1 - v1;
    if (lane == 31) g_off[n] = __shfl_sync(0xFFFFFFFFu, s1, 31);
}

__global__ void k_scan_add(int n) {
    int i = blockIdx.x * 1024 + threadIdx.x;
    if (i < n) {
        int o = g_off[i] + g_bpre[blockIdx.x];
        g_off[i] = o;
        g_cursor[i] = o;
    }
}

__global__ void k_fill(const void* __restrict__ ei, int E) {
    int e = blockIdx.x * blockDim.x + threadIdx.x;
    int is64 = g_is64;
    if (e < E) {
        int s = edge_at(ei, e, is64);
        int d = edge_at(ei, E + e, is64);
        g_esrc[atomicAdd(&g_cursor[d], 1)] = s;
    }
}

// ---------------------------------------------------------------------------
// Fused SAGE layer: out = [relu]( mean_agg(X) @ Wl^T + b + X @ Wr^T )
// - Aggregation fused into GEMM prologue (no g_agg round-trip).
// - fp32 via bf16 hi/lo split: 3 MMA chains (hh + hl + lh), err ~1e-5.
// - A tile (M=128, K=128) resident full-K; weights chunked K=64 to halve
//   smem (104KB) -> 2 CTAs/SM -> gather (LTS) overlaps MMA (tensor).
// - 8 warps, 4(M) x 2(N): per warp M=32 (2x m16), N=64 (4x n16).
// ---------------------------------------------------------------------------
#define SA 136                       // A row stride (bf16), ldmatrix conflict-free
#define SB 72                        // B row stride (bf16)
#define OFF_AH 0
#define OFF_AL (128 * SA * 2)        // 34816
#define OFF_BH (2 * 128 * SA * 2)    // 69632
#define OFF_BL (OFF_BH + 128 * SB * 2)  // 88064
#define SAGE_SMEM (OFF_BH + 2 * 128 * SB * 2)  // 106496

__device__ __forceinline__ void pack_hilo(float4 v, uint2* hu, uint2* lu) {
    __nv_bfloat16 h0 = __float2bfloat16(v.x), h1 = __float2bfloat16(v.y);
    __nv_bfloat16 h2 = __float2bfloat16(v.z), h3 = __float2bfloat16(v.w);
    __nv_bfloat16 l0 = __float2bfloat16(v.x - __bfloat162float(h0));
    __nv_bfloat16 l1 = __float2bfloat16(v.y - __bfloat162float(h1));
    __nv_bfloat16 l2 = __float2bfloat16(v.z - __bfloat162float(h2));
    __nv_bfloat16 l3 = __float2bfloat16(v.w - __bfloat162float(h3));
    __nv_bfloat162 hp0, hp1, lp0, lp1;
    hp0.x = h0; hp0.y = h1; hp1.x = h2; hp1.y = h3;
    lp0.x = l0; lp0.y = l1; lp1.x = l2; lp1.y = l3;
    hu->x = *(uint32_t*)&hp0; hu->y = *(uint32_t*)&hp1;
    lu->x = *(uint32_t*)&lp0; lu->y = *(uint32_t*)&lp1;
}

template <bool RELU>
__global__ void __launch_bounds__(256, 2)
k_sage(const float* __restrict__ Xext, int X_is_h,
       const float* __restrict__ Wl, const float* __restrict__ Wr,
       const float* __restrict__ bias,
       float* __restrict__ outext, int out_is_h, int n) {
    extern __shared__ __align__(16) char sm[];
    __nv_bfloat16* AH = (__nv_bfloat16*)(sm + OFF_AH);
    __nv_bfloat16* AL = (__nv_bfloat16*)(sm + OFF_AL);
    __nv_bfloat16* BH = (__nv_bfloat16*)(sm + OFF_BH);
    __nv_bfloat16* BL = (__nv_bfloat16*)(sm + OFF_BL);

    const float* X = X_is_h ? (const float*)g_h : Xext;
    float* outp = out_is_h ? (float*)g_h : outext;

    const int tid = threadIdx.x;
    const int wid = tid >> 5;
    const int lane = tid & 31;
    const int warp_m = wid >> 1;
    const int warp_n = wid & 1;
    const int row0 = blockIdx.x * 128;

    // ---- Phase A: gather-aggregate 128 rows -> AH/AL (16 rows per warp) ----
    #pragma unroll 1
    for (int rr = 0; rr < 16; rr++) {
        int r = (wid << 4) + rr;
        int node = row0 + r;
        float4 acc = make_float4(0.f, 0.f, 0.f, 0.f);
        if (node < n) {
            int e0 = g_off[node], e1 = g_off[node + 1];
            for (int e = e0; e < e1; e++) {
                int src = g_esrc[e];
                float4 v = *(const float4*)(X + (size_t)src * D + lane * 4);
                acc.x += v.x; acc.y += v.y; acc.z += v.z; acc.w += v.w;
            }
            int c = e1 - e0;
            float inv = (c > 0) ? (1.0f / (float)c) : 0.0f;
            acc.x *= inv; acc.y *= inv; acc.z *= inv; acc.w *= inv;
        }
        uint2 hu, lu;
        pack_hilo(acc, &hu, &lu);
        *(uint2*)&AH[r * SA + lane * 4] = hu;
        *(uint2*)&AL[r * SA + lane * 4] = lu;
    }

    float acc[2][8][4];
    #pragma unroll
    for (int t = 0; t < 2; t++)
        #pragma unroll
        for (int nt = 0; nt < 8; nt++)
            #pragma unroll
            for (int q = 0; q < 4; q++) acc[t][nt][q] = 0.f;

    #pragma unroll
    for (int pass = 0; pass < 2; pass++) {
        if (pass == 1) {
            __syncthreads();   // prior MMA reads of A done
            // A := X rows (skip connection), 16 float4-iters
            #pragma unroll
            for (int it = 0; it < 16; it++) {
                int idx = it * 256 + tid;
                int r = idx >> 5, c4 = (idx & 31) * 4;
                int gr = row0 + r;
                float4 v = make_float4(0.f, 0.f, 0.f, 0.f);
                if (gr < n) v = *(const float4*)(X + (size_t)gr * D + c4);
                uint2 hu, lu;
                pack_hilo(v, &hu, &lu);
                *(uint2*)&AH[r * SA + c4] = hu;
                *(uint2*)&AL[r * SA + c4] = lu;
            }
        }
        const float* W = pass ? Wr : Wl;

        #pragma unroll
        for (int chunk = 0; chunk < 2; chunk++) {
            const int kbase = chunk * 64;
            __syncthreads();   // prior MMA reads of B done (also covers A writes)
            // B := W[:, kbase:kbase+64] hi/lo, 8 float4-iters
            #pragma unroll
            for (int it = 0; it < 8; it++) {
                int idx = it * 256 + tid;
                int r = idx >> 4, c4 = (idx & 15) * 4;
                float4 v = *(const float4*)(W + r * D + kbase + c4);
                uint2 hu, lu;
                pack_hilo(v, &hu, &lu);
                *(uint2*)&BH[r * SB + c4] = hu;
                *(uint2*)&BL[r * SB + c4] = lu;
            }
            __syncthreads();

            #pragma unroll
            for (int ks = 0; ks < 4; ks++) {
                const int k0 = ks * 16;
                uint32_t ah[2][4], al[2][4];
                #pragma unroll
                for (int t = 0; t < 2; t++) {
                    int mrow = warp_m * 32 + t * 16 + (lane & 15);
                    int mcol = kbase + k0 + (lane >> 4) * 8;
                    LDSM_X4(ah[t][0], ah[t][1], ah[t][2], ah[t][3],
                            smem_u32(&AH[mrow * SA + mcol]));
                    LDSM_X4(al[t][0], al[t][1], al[t][2], al[t][3],
                            smem_u32(&AL[mrow * SA + mcol]));
                }
                #pragma unroll
                for (int np = 0; np < 4; np++) {
                    int nn = warp_n * 64 + np * 16 + (lane & 7) + ((lane >> 4) << 3);
                    int kk = k0 + ((lane >> 3) & 1) * 8;
                    uint32_t bh0, bh1, bh2, bh3, bl0, bl1, bl2, bl3;
                    LDSM_X4(bh0, bh1, bh2, bh3, smem_u32(&BH[nn * SB + kk]));
                    LDSM_X4(bl0, bl1, bl2, bl3, smem_u32(&BL[nn * SB + kk]));
                    #pragma unroll
                    for (int t = 0; t < 2; t++) {
                        MMA16816(acc[t][np * 2], ah[t], bh0, bh1);
                        MMA16816(acc[t][np * 2], ah[t], bl0, bl1);
                        MMA16816(acc[t][np * 2], al[t], bh0, bh1);
                        MMA16816(acc[t][np * 2 + 1], ah[t], bh2, bh3);
                        MMA16816(acc[t][np * 2 + 1], ah[t], bl2, bl3);
                        MMA16816(acc[t][np * 2 + 1], al[t], bh2, bh3);
                    }
                }
            }
        }
    }

    // Epilogue
    #pragma unroll
    for (int t = 0; t < 2; t++) {
        int rbase = row0 + warp_m * 32 + t * 16 + (lane >> 2);
        #pragma unroll
        for (int nt = 0; nt < 8; nt++) {
            int col = warp_n * 64 + nt * 8 + (lane & 3) * 2;
            float2 bb = *(const float2*)&bias[col];
            if (rbase < n) {
                float2 v;
                v.x = acc[t][nt][0] + bb.x;
                v.y = acc[t][nt][1] + bb.y;
                if (RELU) { v.x = fmaxf(v.x, 0.f); v.y = fmaxf(v.y, 0.f); }
                *(float2*)(outp + (size_t)rbase * D + col) = v;
            }
            if (rbase + 8 < n) {
                float2 v;
                v.x = acc[t][nt][2] + bb.x;
                v.y = acc[t][nt][3] + bb.y;
                if (RELU) { v.x = fmaxf(v.x, 0.f); v.y = fmaxf(v.y, 0.f); }
                *(float2*)(outp + (size_t)(rbase + 8) * D + col) = v;
            }
        }
    }
}

// ---------------------------------------------------------------------------
extern "C" void kernel_launch(void* const* d_in, const int* in_sizes, int n_in,
                              void* d_out, int out_size) {
    const float* x   = (const float*)d_in[0];
    const void*  ei  = d_in[1];
    const float* Wl0 = (const float*)d_in[2];
    const float* bl0 = (const float*)d_in[3];
    const float* Wr0 = (const float*)d_in[4];
    const float* Wl1 = (const float*)d_in[5];
    const float* bl1 = (const float*)d_in[6];
    const float* Wr1 = (const float*)d_in[7];
    float*       out = (float*)d_out;

    const int n = in_sizes[0] / D;
    const int E = in_sizes[1] / 2;
    const int nb = (n + 1023) / 1024;

    static int attr_set = 0;
    if (!attr_set) {
        cudaFuncSetAttribute(k_sage<true>,
                             cudaFuncAttributeMaxDynamicSharedMemorySize, SAGE_SMEM);
        cudaFuncSetAttribute(k_sage<false>,
                             cudaFuncAttributeMaxDynamicSharedMemorySize, SAGE_SMEM);
        attr_set = 1;
    }

    // CSR build (graph identical for both layers)
    k_init<<<(n + 255) / 256, 256>>>((const int*)ei, n);
    k_hist<<<(E + 255) / 256, 256>>>(ei, E);
    k_scan_local<<<nb, 1024>>>(n);
    k_scan_mid<<<1, 32>>>(nb, n);
    k_scan_add<<<nb, 1024>>>(n);
    k_fill<<<(E + 255) / 256, 256>>>(ei, E);

    const int blocks = (n + 127) / 128;

    // Layer 0: g_h = relu(agg(x) @ Wl0^T + b0 + x @ Wr0^T)
    k_sage<true><<<blocks, 256, SAGE_SMEM>>>(x, 0, Wl0, Wr0, bl0, nullptr, 1, n);
    // Layer 1: out = agg(g_h) @ Wl1^T + b1 + g_h @ Wr1^T
    k_sage<false><<<blocks, 256, SAGE_SMEM>>>(nullptr, 1, Wl1, Wr1, bl1, out, 0, n);
}

// round 11
// speedup vs baseline: 1.2913x; 1.2913x over previous
#include <cuda_runtime.h>
#include <cuda_bf16.h>
#include <cuda_fp16.h>
#include <cstdint>

#define MAX_N 50000
#define MAX_E 800000
#define D 128

// Scratch in device globals.
__device__ int   g_is64;
__device__ int   g_deg[MAX_N];
__device__ int   g_off[MAX_N + 1];
__device__ int   g_cursor[MAX_N];
__device__ int   g_esrc[MAX_E];
__device__ int   g_bsum[64];
__device__ int   g_bpre[64];
__device__ __align__(16) float g_agg[(size_t)MAX_N * D];
__device__ __align__(16) float g_h[(size_t)MAX_N * D];

// ---------------------------------------------------------------------------
// Base-ISA tensor primitives (harness PTX target is sm_103 WITHOUT 'a':
// tcgen05 unavailable; mma.sync/ldmatrix are the tensor path).
// ---------------------------------------------------------------------------
__device__ __forceinline__ uint32_t smem_u32(const void* p) {
    uint32_t a;
    asm("{ .reg .u64 t; cvta.to.shared.u64 t, %1; cvt.u32.u64 %0, t; }" : "=r"(a) : "l"(p));
    return a;
}

#define LDSM_X4(r0, r1, r2, r3, addr) \
    asm volatile("ldmatrix.sync.aligned.m8n8.x4.shared.b16 {%0,%1,%2,%3}, [%4];" \
                 : "=r"(r0), "=r"(r1), "=r"(r2), "=r"(r3) : "r"(addr))

#define MMAF16(c, a, b0, b1) \
    asm volatile("mma.sync.aligned.m16n8k16.row.col.f32.f16.f16.f32 " \
                 "{%0,%1,%2,%3}, {%4,%5,%6,%7}, {%8,%9}, {%0,%1,%2,%3};" \
                 : "+f"((c)[0]), "+f"((c)[1]), "+f"((c)[2]), "+f"((c)[3]) \
                 : "r"((a)[0]), "r"((a)[1]), "r"((a)[2]), "r"((a)[3]), \
                   "r"(b0), "r"(b1))

// ---------------------------------------------------------------------------
// CSR build.  k_init: zero degrees + edge-dtype detect (dataset says int64,
// JAX default config emits int32 -> odd words all zero when truly int64).
// ---------------------------------------------------------------------------
__global__ void k_init(const int* __restrict__ ei32, int n) {
    int i = blockIdx.x * blockDim.x + threadIdx.x;
    if (i < n) g_deg[i] = 0;
    if (i == 0) {
        int allzero = 1;
        #pragma unroll
        for (int k = 1; k < 64; k += 2)
            if (ei32[k] != 0) allzero = 0;
        g_is64 = allzero;
    }
}

__device__ __forceinline__ int edge_at(const void* ei, int idx, int is64) {
    return is64 ? (int)((const long long*)ei)[idx] : ((const int*)ei)[idx];
}

__global__ void k_hist(const void* __restrict__ ei, int E) {
    int e = blockIdx.x * blockDim.x + threadIdx.x;
    int is64 = g_is64;
    if (e < E) atomicAdd(&g_deg[edge_at(ei, E + e, is64)], 1);
}

__global__ void k_scan_local(int n) {
    __shared__ int warp_sums[32];
    int lane = threadIdx.x & 31, wid = threadIdx.x >> 5;
    int i = blockIdx.x * 1024 + threadIdx.x;
    int v = (i < n) ? g_deg[i] : 0;
    int s = v;
    #pragma unroll
    for (int o = 1; o < 32; o <<= 1) {
        int t = __shfl_up_sync(0xFFFFFFFFu, s, o);
        if (lane >= o) s += t;
    }
    if (lane == 31) warp_sums[wid] = s;
    __syncthreads();
    if (wid == 0) {
        int ws = warp_sums[lane];
        #pragma unroll
        for (int o = 1; o < 32; o <<= 1) {
            int t = __shfl_up_sync(0xFFFFFFFFu, ws, o);
            if (lane >= o) ws += t;
        }
        warp_sums[lane] = ws;
    }
    __syncthreads();
    int incl = s + (wid > 0 ? warp_sums[wid - 1] : 0);
    if (i < n) g_off[i] = incl - v;
    if (threadIdx.x == 1023) g_bsum[blockIdx.x] = incl;
}

__global__ void k_scan_mid(int nb, int n) {
    int lane = threadIdx.x;
    int v0 = (lane < nb) ? g_bsum[lane] : 0;
    int v1 = (lane + 32 < nb) ? g_bsum[lane + 32] : 0;
    int s0 = v0;
    #pragma unroll
    for (int o = 1; o < 32; o <<= 1) {
        int t = __shfl_up_sync(0xFFFFFFFFu, s0, o);
        if (lane >= o) s0 += t;
    }
    int tot0 = __shfl_sync(0xFFFFFFFFu, s0, 31);
    int s1 = v1;
    #pragma unroll
    for (int o = 1; o < 32; o <<= 1) {
        int t = __shfl_up_sync(0xFFFFFFFFu, s1, o);
        if (lane >= o) s1 += t;
    }
    s1 += tot0;
    if (lane < nb) g_bpre[lane] = s0 - v0;
    if (lane + 32 < nb) g_bpre[lane + 32] = s1 - v1;
    if (lane == 31) g_off[n] = __shfl_sync(0xFFFFFFFFu, s1, 31);
}

__global__ void k_scan_add(int n) {
    int i = blockIdx.x * 1024 + threadIdx.x;
    if (i < n) {
        int o = g_off[i] + g_bpre[blockIdx.x];
        g_off[i] = o;
        g_cursor[i] = o;
    }
}

__global__ void k_fill(const void* __restrict__ ei, int E) {
    int e = blockIdx.x * blockDim.x + threadIdx.x;
    int is64 = g_is64;
    if (e < E) {
        int s = edge_at(ei, e, is64);
        int d = edge_at(ei, E + e, is64);
        g_esrc[atomicAdd(&g_cursor[d], 1)] = s;
    }
}

// ---------------------------------------------------------------------------
// Aggregation: warp per node (max parallelism -> L2 latency fully hidden,
// LTS-cap bound). Fusing this into the GEMM was a measured regression
// (161.9 -> 209us): DO NOT fuse — it cuts gather concurrency 16x.
// ---------------------------------------------------------------------------
__global__ void k_aggregate(const float* __restrict__ xext, int use_h, int n) {
    const float* xin = use_h ? (const float*)g_h : xext;
    int warp = (blockIdx.x * blockDim.x + threadIdx.x) >> 5;
    int lane = threadIdx.x & 31;
    if (warp >= n) return;
    int s0 = g_off[warp];
    int s1 = g_off[warp + 1];
    float4 acc = make_float4(0.f, 0.f, 0.f, 0.f);
    int e = s0;
    for (; e + 2 <= s1; e += 2) {            // unroll-2: 2 gathers in flight
        int srcA = g_esrc[e], srcB = g_esrc[e + 1];
        float4 a = *(const float4*)(xin + (size_t)srcA * D + lane * 4);
        float4 b = *(const float4*)(xin + (size_t)srcB * D + lane * 4);
        acc.x += a.x + b.x; acc.y += a.y + b.y;
        acc.z += a.z + b.z; acc.w += a.w + b.w;
    }
    if (e < s1) {
        int src = g_esrc[e];
        float4 a = *(const float4*)(xin + (size_t)src * D + lane * 4);
        acc.x += a.x; acc.y += a.y; acc.z += a.z; acc.w += a.w;
    }
    int cnt = s1 - s0;
    float inv = (cnt > 0) ? (1.0f / (float)cnt) : 0.0f;
    acc.x *= inv; acc.y *= inv; acc.z *= inv; acc.w *= inv;
    *(float4*)(g_agg + (size_t)warp * D + lane * 4) = acc;
}

// ---------------------------------------------------------------------------
// Tensor-core GEMM via mma.sync fp16, fp32 acc. fp32 emulated with an EXACT
// fp16 hi/lo split of A (2 chains: (a_hi + a_lo)·b_hi = a·b_hi); B rounded
// once to fp16 -> only dropped term is a·b_lo ~ 2^-12 rel (~1e-4 end-to-end,
// gate is 1e-3). 512 MMAs/warp (was 768 with bf16 3-chain), no BL tile.
// Tile M=128, N=128, K=128 resident, 2 passes (Wl·agg + Wr·X) share acc.
// 8 warps 4(M)x2(N); per warp M=32 (2x m16), N=64 (8x n8).
// Smem 104448B -> 2 CTAs/SM with __launch_bounds__(256,2).
// ---------------------------------------------------------------------------
#define SA 136                         // row stride in halfs: ldmatrix conflict-free
#define TILEB (128 * SA * 2)           // 34816 bytes per tile
#define OFF_AH 0
#define OFF_AL TILEB
#define OFF_BH (2 * TILEB)
#define SAGE_SMEM (3 * TILEB)          // 104448

__device__ __forceinline__ void pack_hilo_f16(float4 v, uint2* hu, uint2* lu) {
    __half h0 = __float2half_rn(v.x), h1 = __float2half_rn(v.y);
    __half h2 = __float2half_rn(v.z), h3 = __float2half_rn(v.w);
    __half l0 = __float2half_rn(v.x - __half2float(h0));
    __half l1 = __float2half_rn(v.y - __half2float(h1));
    __half l2 = __float2half_rn(v.z - __half2float(h2));
    __half l3 = __float2half_rn(v.w - __half2float(h3));
    __half2 hp0 = __halves2half2(h0, h1), hp1 = __halves2half2(h2, h3);
    __half2 lp0 = __halves2half2(l0, l1), lp1 = __halves2half2(l2, l3);
    hu->x = *(uint32_t*)&hp0; hu->y = *(uint32_t*)&hp1;
    lu->x = *(uint32_t*)&lp0; lu->y = *(uint32_t*)&lp1;
}

__device__ __forceinline__ uint2 pack_f16(float4 v) {
    __half2 p0 = __halves2half2(__float2half_rn(v.x), __float2half_rn(v.y));
    __half2 p1 = __halves2half2(__float2half_rn(v.z), __float2half_rn(v.w));
    uint2 u;
    u.x = *(uint32_t*)&p0; u.y = *(uint32_t*)&p1;
    return u;
}

template <bool RELU>
__global__ void __launch_bounds__(256, 2)
k_gemm_mma(const float* __restrict__ Bext, int B_is_h,
           const float* __restrict__ Wl, const float* __restrict__ Wr,
           const float* __restrict__ bias,
           float* __restrict__ outext, int out_is_h, int n) {
    extern __shared__ __align__(16) char sm[];
    __half* AH = (__half*)(sm + OFF_AH);
    __half* AL = (__half*)(sm + OFF_AL);
    __half* BH = (__half*)(sm + OFF_BH);

    const float* Bp = B_is_h ? (const float*)g_h : Bext;
    float* outp = out_is_h ? (float*)g_h : outext;

    const int tid = threadIdx.x;
    const int wid = tid >> 5;
    const int lane = tid & 31;
    const int warp_m = wid >> 1;
    const int warp_n = wid & 1;
    const int row0 = blockIdx.x * 128;

    float acc[2][8][4];
    #pragma unroll
    for (int t = 0; t < 2; t++)
        #pragma unroll
        for (int nt = 0; nt < 8; nt++)
            #pragma unroll
            for (int q = 0; q < 4; q++) acc[t][nt][q] = 0.f;

    #pragma unroll
    for (int pass = 0; pass < 2; pass++) {
        const float* X = pass ? Bp : (const float*)g_agg;
        const float* W = pass ? Wr : Wl;

        __syncthreads();   // previous pass's smem reads complete
        // A tile: hi/lo exact fp16 split, 16 float4-iters
        #pragma unroll 4
        for (int it = 0; it < 16; it++) {
            int idx = it * 256 + tid;
            int r = idx >> 5, c4 = (idx & 31) * 4;
            int gr = row0 + r;
            float4 v = make_float4(0.f, 0.f, 0.f, 0.f);
            if (gr < n) v = *(const float4*)(X + (size_t)gr * D + c4);
            uint2 hu, lu;
            pack_hilo_f16(v, &hu, &lu);
            *(uint2*)&AH[r * SA + c4] = hu;
            *(uint2*)&AL[r * SA + c4] = lu;
        }
        // B tile: single fp16 rounding, 16 float4-iters
        #pragma unroll 4
        for (int it = 0; it < 16; it++) {
            int idx = it * 256 + tid;
            int r = idx >> 5, c4 = (idx & 31) * 4;
            *(uint2*)&BH[r * SA + c4] = pack_f16(*(const float4*)(W + r * D + c4));
        }
        __syncthreads();

        #pragma unroll
        for (int ks = 0; ks < 8; ks++) {
            const int k0 = ks * 16;
            uint32_t ah[2][4], al[2][4];
            #pragma unroll
            for (int t = 0; t < 2; t++) {
                int mrow = warp_m * 32 + t * 16 + (lane & 15);
                int mcol = k0 + (lane >> 4) * 8;
                LDSM_X4(ah[t][0], ah[t][1], ah[t][2], ah[t][3],
                        smem_u32(&AH[mrow * SA + mcol]));
                LDSM_X4(al[t][0], al[t][1], al[t][2], al[t][3],
                        smem_u32(&AL[mrow * SA + mcol]));
            }
            #pragma unroll
            for (int np = 0; np < 4; np++) {
                int nn = warp_n * 64 + np * 16 + (lane & 7) + ((lane >> 4) << 3);
                int kk = k0 + ((lane >> 3) & 1) * 8;
                uint32_t bh0, bh1, bh2, bh3;
                LDSM_X4(bh0, bh1, bh2, bh3, smem_u32(&BH[nn * SA + kk]));
                #pragma unroll
                for (int t = 0; t < 2; t++) {
                    MMAF16(acc[t][np * 2], ah[t], bh0, bh1);
                    MMAF16(acc[t][np * 2], al[t], bh0, bh1);
                    MMAF16(acc[t][np * 2 + 1], ah[t], bh2, bh3);
                    MMAF16(acc[t][np * 2 + 1], al[t], bh2, bh3);
                }
            }
        }
    }

    // Epilogue: c0,c1 -> (row, col..col+1); c2,c3 -> (row+8, col..col+1)
    #pragma unroll
    for (int t = 0; t < 2; t++) {
        int rbase = row0 + warp_m * 32 + t * 16 + (lane >> 2);
        #pragma unroll
        for (int nt = 0; nt < 8; nt++) {
            int col = warp_n * 64 + nt * 8 + (lane & 3) * 2;
            float2 bb = *(const float2*)&bias[col];
            if (rbase < n) {
                float2 v;
                v.x = acc[t][nt][0] + bb.x;
                v.y = acc[t][nt][1] + bb.y;
                if (RELU) { v.x = fmaxf(v.x, 0.f); v.y = fmaxf(v.y, 0.f); }
                *(float2*)(outp + (size_t)rbase * D + col) = v;
            }
            if (rbase + 8 < n) {
                float2 v;
                v.x = acc[t][nt][2] + bb.x;
                v.y = acc[t][nt][3] + bb.y;
                if (RELU) { v.x = fmaxf(v.x, 0.f); v.y = fmaxf(v.y, 0.f); }
                *(float2*)(outp + (size_t)(rbase + 8) * D + col) = v;
            }
        }
    }
}

// ---------------------------------------------------------------------------
extern "C" void kernel_launch(void* const* d_in, const int* in_sizes, int n_in,
                              void* d_out, int out_size) {
    const float* x   = (const float*)d_in[0];
    const void*  ei  = d_in[1];
    const float* Wl0 = (const float*)d_in[2];
    const float* bl0 = (const float*)d_in[3];
    const float* Wr0 = (const float*)d_in[4];
    const float* Wl1 = (const float*)d_in[5];
    const float* bl1 = (const float*)d_in[6];
    const float* Wr1 = (const float*)d_in[7];
    float*       out = (float*)d_out;

    const int n = in_sizes[0] / D;
    const int E = in_sizes[1] / 2;
    const int nb = (n + 1023) / 1024;

    static int attr_set = 0;
    if (!attr_set) {
        cudaFuncSetAttribute(k_gemm_mma<true>,
                             cudaFuncAttributeMaxDynamicSharedMemorySize, SAGE_SMEM);
        cudaFuncSetAttribute(k_gemm_mma<false>,
                             cudaFuncAttributeMaxDynamicSharedMemorySize, SAGE_SMEM);
        attr_set = 1;
    }

    // CSR build (graph identical for both layers)
    k_init<<<(n + 255) / 256, 256>>>((const int*)ei, n);
    k_hist<<<(E + 255) / 256, 256>>>(ei, E);
    k_scan_local<<<nb, 1024>>>(n);
    k_scan_mid<<<1, 32>>>(nb, n);
    k_scan_add<<<nb, 1024>>>(n);
    k_fill<<<(E + 255) / 256, 256>>>(ei, E);

    const int agg_blocks  = (n * 32 + 255) / 256;
    const int gemm_blocks = (n + 127) / 128;

    // Layer 0: g_h = relu(agg(x) @ Wl0^T + b0 + x @ Wr0^T)
    k_aggregate<<<agg_blocks, 256>>>(x, 0, n);
    k_gemm_mma<true><<<gemm_blocks, 256, SAGE_SMEM>>>(x, 0, Wl0, Wr0, bl0, nullptr, 1, n);

    // Layer 1: out = agg(g_h) @ Wl1^T + b1 + g_h @ Wr1^T
    k_aggregate<<<agg_blocks, 256>>>(nullptr, 1, n);
    k_gemm_mma<false><<<gemm_blocks, 256, SAGE_SMEM>>>(nullptr, 1, Wl1, Wr1, bl1, out, 0, n);
}